// round 17
// baseline (speedup 1.0000x reference)
#include <cuda_runtime.h>
#include <cuda_bf16.h>

#define F 128
#define CAP_N 51200
#define CAP_E 650000

__device__ float4 g_agg4[(size_t)CAP_N * (F / 4)];  // raw weighted sums S

// ---------------------------------------------------------------------------
// K0: zero agg scratch
// ---------------------------------------------------------------------------
__global__ void k_zero(int N) {
    int i = blockIdx.x * blockDim.x + threadIdx.x;
    int total4 = N * (F / 4);
    if (i < total4)
        g_agg4[i] = make_float4(0.f, 0.f, 0.f, 0.f);
}

// ---------------------------------------------------------------------------
// K1: one warp per edge; S[t] += exp(w[e]) * x[src]
// (softmax denom algebraically folded into the L2 norm; residual ~1e-9 rel)
// ---------------------------------------------------------------------------
__global__ void k_scatter(const float* __restrict__ x,
                          const int* __restrict__ ei,
                          const float* __restrict__ w, int E, int N) {
    int gid = blockIdx.x * blockDim.x + threadIdx.x;
    int e = gid >> 5;
    int lane = gid & 31;
    if (e >= E) return;
    int s = ei[e];
    int t = ei[E + e];
    if ((unsigned)s >= (unsigned)N || (unsigned)t >= (unsigned)N) return;
    float ew = 0.f;
    if (lane == 0) ew = expf(w[e]);
    ew = __shfl_sync(0xffffffffu, ew, 0);
    float4 xv = reinterpret_cast<const float4*>(x)[(size_t)s * 32 + lane];
    float4 v = make_float4(ew * xv.x, ew * xv.y, ew * xv.z, ew * xv.w);
    atomicAdd(&g_agg4[(size_t)t * 32 + lane], v);
}

// ---------------------------------------------------------------------------
// HMMA fused dual GEMM — 64-row blocks, 256 threads, 2 CTAs/SM.
// smem/CTA: XH,XL,AH,AL (4 x 17408) + one W slot (34816) + params = ~105KB.
// W slot restaged: WsH -> WsL -> WnH -> WnL; peer CTA's mma hides the gaps.
// ---------------------------------------------------------------------------
#define BLK_ROWS 64
#define RS 136
#define XBUF 17408            // 64 * 136 * 2
#define WBUF 34816            // 128 * 136 * 2
#define CSTRIDE 132

#define OFF_XH 0
#define OFF_XL (XBUF)
#define OFF_AH (2 * XBUF)
#define OFF_AL (3 * XBUF)
#define OFF_W  (4 * XBUF)                 // 69632
#define OFF_PAR (4 * XBUF + WBUF)         // 104448
#define SMEM_TOTAL (OFF_PAR + 2304)       // 106752 (<= 113KB -> 2 CTAs/SM)

__device__ __forceinline__ void mma16816(float* d,
                                         unsigned a0, unsigned a1,
                                         unsigned a2, unsigned a3,
                                         unsigned b0, unsigned b1) {
    asm volatile(
        "mma.sync.aligned.m16n8k16.row.col.f32.bf16.bf16.f32 "
        "{%0,%1,%2,%3}, {%4,%5,%6,%7}, {%8,%9}, {%0,%1,%2,%3};"
        : "+f"(d[0]), "+f"(d[1]), "+f"(d[2]), "+f"(d[3])
        : "r"(a0), "r"(a1), "r"(a2), "r"(a3), "r"(b0), "r"(b1));
}

__device__ __forceinline__ void ldsm4(unsigned& r0, unsigned& r1,
                                      unsigned& r2, unsigned& r3,
                                      unsigned addr) {
    asm volatile("ldmatrix.sync.aligned.m8n8.x4.shared.b16 {%0,%1,%2,%3}, [%4];"
                 : "=r"(r0), "=r"(r1), "=r"(r2), "=r"(r3) : "r"(addr));
}

__device__ __forceinline__ void ldsm4t(unsigned& r0, unsigned& r1,
                                       unsigned& r2, unsigned& r3,
                                       unsigned addr) {
    asm volatile("ldmatrix.sync.aligned.m8n8.x4.trans.shared.b16 {%0,%1,%2,%3}, [%4];"
                 : "=r"(r0), "=r"(r1), "=r"(r2), "=r"(r3) : "r"(addr));
}

__device__ __forceinline__ unsigned pack2(float a, float b) {
    __nv_bfloat162 t = __floats2bfloat162_rn(a, b);
    return *(unsigned*)&t;
}

__device__ __forceinline__ void split4(float4 v, uint2& hw, uint2& lw) {
    __nv_bfloat16 h0 = __float2bfloat16(v.x), h1 = __float2bfloat16(v.y);
    __nv_bfloat16 h2 = __float2bfloat16(v.z), h3 = __float2bfloat16(v.w);
    hw.x = ((unsigned)*(unsigned short*)&h1 << 16) | *(unsigned short*)&h0;
    hw.y = ((unsigned)*(unsigned short*)&h3 << 16) | *(unsigned short*)&h2;
    lw.x = pack2(v.x - __bfloat162float(h0), v.y - __bfloat162float(h1));
    lw.y = pack2(v.z - __bfloat162float(h2), v.w - __bfloat162float(h3));
}

// stage ONE half (hi or lo) of a 128x128 W into the W slot ([k][n] natural)
__device__ __forceinline__ void stage_w(char* Wslot, const float* __restrict__ Wg,
                                        int tid, bool lo) {
    #pragma unroll
    for (int it = 0; it < 16; ++it) {
        int idx = tid + it * 256;             // [0, 4096)
        int k = idx >> 5, c4 = idx & 31;
        float4 w = ((const float4*)Wg)[idx];
        uint2 hw, lw;
        split4(w, hw, lw);
        *(uint2*)(Wslot + (k * RS + c4 * 4) * 2) = lo ? lw : hw;
    }
}

__device__ __forceinline__ void subpass(unsigned a_smem, unsigned w_smem,
                                        int a_off, int b_off,
                                        float* acc) {
    #pragma unroll
    for (int ks = 0; ks < 8; ++ks) {
        unsigned a0, a1, a2, a3;
        ldsm4(a0, a1, a2, a3, a_smem + (unsigned)(a_off + ks * 16) * 2);
        #pragma unroll
        for (int p = 0; p < 4; ++p) {
            unsigned s0, s1, s2, s3;
            ldsm4t(s0, s1, s2, s3,
                   w_smem + (unsigned)(b_off + ks * 16 * RS + p * 16) * 2);
            mma16816(&acc[(2 * p) * 4], a0, a1, a2, a3, s0, s1);
            mma16816(&acc[(2 * p + 1) * 4], a0, a1, a2, a3, s2, s3);
        }
    }
}

__global__ __launch_bounds__(256, 2)
void k_fused(const float* __restrict__ x,
             const float* __restrict__ Wself, const float* __restrict__ bself,
             const float* __restrict__ Wnb, const float* __restrict__ bnb,
             const float* __restrict__ gamma, const float* __restrict__ beta,
             float* __restrict__ out, int N) {
    extern __shared__ char smem[];
    __nv_bfloat16* XH = (__nv_bfloat16*)(smem + OFF_XH);
    __nv_bfloat16* XL = (__nv_bfloat16*)(smem + OFF_XL);
    __nv_bfloat16* AH = (__nv_bfloat16*)(smem + OFF_AH);
    __nv_bfloat16* AL = (__nv_bfloat16*)(smem + OFF_AL);
    char* Wslot = smem + OFF_W;
    float* sb   = (float*)(smem + OFF_PAR);
    float* snb  = (float*)(smem + OFF_PAR + 512);
    float* sg   = (float*)(smem + OFF_PAR + 1024);
    float* sbt  = (float*)(smem + OFF_PAR + 1536);
    float* sinv = (float*)(smem + OFF_PAR + 2048);   // 64 floats

    int tid = threadIdx.x;
    int wid = tid >> 5, lane = tid & 31;
    int base = blockIdx.x * BLK_ROWS;
    const float* aggf = (const float*)g_agg4;

    // ---- phase 0: params + agg row inverse norms (8 rows/warp) ----
    if (tid < 128) {
        sb[tid] = bself[tid];
        snb[tid] = bnb[tid];
        sg[tid] = gamma[tid];
        sbt[tid] = beta[tid];
    }
    #pragma unroll
    for (int i = 0; i < 8; ++i) {
        int r = wid * 8 + i;
        int node = base + r; if (node >= N) node = N - 1;
        float4 a = g_agg4[(size_t)node * 32 + lane];
        float ss = a.x * a.x + a.y * a.y + a.z * a.z + a.w * a.w;
        #pragma unroll
        for (int off = 16; off; off >>= 1)
            ss += __shfl_xor_sync(0xffffffffu, ss, off);
        if (lane == 0) sinv[r] = 1.0f / (sqrtf(ss) + 1e-9f);
    }
    __syncthreads();

    // ---- stage X (hi/lo), AG = inv*S (hi/lo), W slot <- WselfH ----
    #pragma unroll
    for (int it = 0; it < 8; ++it) {
        int idx = tid + it * 256;             // [0, 2048)
        int row = idx >> 5, c4 = idx & 31;
        int node = base + row; if (node >= N) node = N - 1;
        uint2 hw, lw;

        float4 v = ((const float4*)x)[(size_t)node * 32 + c4];
        split4(v, hw, lw);
        *(uint2*)(XH + row * RS + c4 * 4) = hw;
        *(uint2*)(XL + row * RS + c4 * 4) = lw;

        float iv = sinv[row];
        float4 a = ((const float4*)aggf)[(size_t)node * 32 + c4];
        a.x *= iv; a.y *= iv; a.z *= iv; a.w *= iv;
        split4(a, hw, lw);
        *(uint2*)(AH + row * RS + c4 * 4) = hw;
        *(uint2*)(AL + row * RS + c4 * 4) = lw;
    }
    stage_w(Wslot, Wself, tid, false);
    __syncthreads();

    // ---- warp tiling: 8 warps = 4 M-groups x 2 N-halves ----
    int warp_m = wid >> 1, warp_n = wid & 1;
    int m0 = warp_m * 16;
    int q = lane >> 3, lr = lane & 7;
    int a_off = (m0 + (q & 1) * 8 + lr) * RS + (q >> 1) * 8;
    int b_off = (lane & 15) * RS + warp_n * 64 + (lane >> 4) * 8;

    unsigned xh_s = (unsigned)__cvta_generic_to_shared(XH);
    unsigned xl_s = (unsigned)__cvta_generic_to_shared(XL);
    unsigned ah_s = (unsigned)__cvta_generic_to_shared(AH);
    unsigned al_s = (unsigned)__cvta_generic_to_shared(AL);
    unsigned w_s  = (unsigned)__cvta_generic_to_shared(Wslot);

    float acc[32];
    #pragma unroll
    for (int i = 0; i < 32; ++i) acc[i] = 0.f;

    // ---- self: xh@WsH, xl@WsH ----
    subpass(xh_s, w_s, a_off, b_off, acc);
    subpass(xl_s, w_s, a_off, b_off, acc);
    __syncthreads();
    stage_w(Wslot, Wself, tid, true);         // W <- WselfL
    __syncthreads();
    subpass(xh_s, w_s, a_off, b_off, acc);    // xh@WsL

    // hold self result in registers
    float sv[32];
    #pragma unroll
    for (int i = 0; i < 32; ++i) { sv[i] = acc[i]; acc[i] = 0.f; }

    __syncthreads();
    stage_w(Wslot, Wnb, tid, false);          // W <- WnbH
    __syncthreads();
    subpass(ah_s, w_s, a_off, b_off, acc);    // ah@WnH
    subpass(al_s, w_s, a_off, b_off, acc);    // al@WnH
    __syncthreads();
    stage_w(Wslot, Wnb, tid, true);           // W <- WnbL
    __syncthreads();
    subpass(ah_s, w_s, a_off, b_off, acc);    // ah@WnL
    __syncthreads();                          // before Cb overlays XH/XL

    // ---- combine into Cb (overlays XH/XL: 64*132*4 = 33792 <= 2*XBUF) ----
    float* Cb = (float*)smem;
    {
        int row0 = m0 + (lane >> 2);
        int row1 = row0 + 8;
        int tr = lane & 3;
        #pragma unroll
        for (int nt = 0; nt < 8; ++nt) {
            int col = warp_n * 64 + nt * 8 + 2 * tr;
            float b0 = sb[col] + snb[col];
            float b1 = sb[col + 1] + snb[col + 1];
            const float* dN = &acc[nt * 4];
            const float* dS = &sv[nt * 4];
            float2 c0, c1;
            c0.x = 0.5f * (dS[0] + dN[0] + b0);
            c0.y = 0.5f * (dS[1] + dN[1] + b1);
            c1.x = 0.5f * (dS[2] + dN[2] + b0);
            c1.y = 0.5f * (dS[3] + dN[3] + b1);
            *(float2*)(Cb + row0 * CSTRIDE + col) = c0;
            *(float2*)(Cb + row1 * CSTRIDE + col) = c1;
        }
    }
    __syncthreads();

    // ---- projective normalize + LayerNorm, write out (8 rows/warp) ----
    float4 gm = ((const float4*)sg)[lane];
    float4 bt4 = ((const float4*)sbt)[lane];
    #pragma unroll
    for (int i = 0; i < 8; ++i) {
        int r = wid * 8 + i;
        int node = base + r;
        if (node >= N) continue;
        float4 c = *(const float4*)(Cb + r * CSTRIDE + lane * 4);
        float s1 = c.x + c.y + c.z + c.w;
        float s2 = c.x * c.x + c.y * c.y + c.z * c.z + c.w * c.w;
        #pragma unroll
        for (int off = 16; off; off >>= 1) {
            s1 += __shfl_xor_sync(0xffffffffu, s1, off);
            s2 += __shfl_xor_sync(0xffffffffu, s2, off);
        }
        float d = sqrtf(s2) + 1e-9f;
        float invd = 1.0f / d;
        float mean = s1 * invd * (1.0f / 128.0f);
        float e2 = s2 * invd * invd * (1.0f / 128.0f);
        float var = e2 - mean * mean;
        float isd = rsqrtf(var + 1e-5f);
        float4 o;
        o.x = (c.x * invd - mean) * isd * gm.x + bt4.x;
        o.y = (c.y * invd - mean) * isd * gm.y + bt4.y;
        o.z = (c.z * invd - mean) * isd * gm.z + bt4.z;
        o.w = (c.w * invd - mean) * isd * gm.w + bt4.w;
        ((float4*)out)[(size_t)node * 32 + lane] = o;
    }
}

// ---------------------------------------------------------------------------
extern "C" void kernel_launch(void* const* d_in, const int* in_sizes, int n_in,
                              void* d_out, int out_size) {
    const float* x     = (const float*)d_in[0];
    const int*   ei    = (const int*)d_in[1];
    const float* ew    = (const float*)d_in[2];
    const float* Wself = (const float*)d_in[3];
    const float* bself = (const float*)d_in[4];
    const float* Wnb   = (const float*)d_in[5];
    const float* bnb   = (const float*)d_in[6];
    const float* gamma = (const float*)d_in[7];
    const float* beta  = (const float*)d_in[8];
    float* out         = (float*)d_out;

    int N = in_sizes[0] / F;
    int E = in_sizes[2];

    int zt = N * (F / 4);
    k_zero<<<(zt + 255) / 256, 256>>>(N);

    long long tot = (long long)E * 32;
    int b2 = (int)((tot + 255) / 256);
    k_scatter<<<b2, 256>>>(x, ei, ew, E, N);

    cudaFuncSetAttribute(k_fused, cudaFuncAttributeMaxDynamicSharedMemorySize,
                         SMEM_TOTAL);
    int b3 = (N + BLK_ROWS - 1) / BLK_ROWS;
    k_fused<<<b3, 256, SMEM_TOTAL>>>(x, Wself, bself, Wnb, bnb, gamma, beta,
                                     out, N);
}